// round 15
// baseline (speedup 1.0000x reference)
#include <cuda_runtime.h>
#include <cuda_bf16.h>
#include <cuda_fp16.h>
#include <cstddef>
#include <cstdint>

#define N_ENT   250002
#define DIM     128
#define T_STEPS 16
#define E_EDGES 300000
#define S_SEEDS 256
#define TWIN    5
#define C_NUM   50000
#define C_PAD   50048           /* 391 * 128 */
#define U_BASE  200000
#define NROWS   (T_STEPS * S_SEEDS)

#define ND ((size_t)N_ENT * DIM)
#define SCAN_BS 512
#define NB ((N_ENT + SCAN_BS - 1) / SCAN_BS)   /* 489 */
#define SNK 2048                               /* padded snap-key table per step */

// ---- scratch (device globals) ----
__device__ __half g_nodes[2 * N_ENT * DIM];       // ping-pong node embeddings (fp16)
__device__ float g_snap[T_STEPS * TWIN * S_SEEDS * DIM]; // seed-row snapshots (fp32)
__device__ int   g_cnt[T_STEPS * N_ENT];
__device__ int   g_off[T_STEPS * N_ENT];          // local-exclusive, advanced by fill
__device__ int   g_bsum[T_STEPS][SCAN_BS];
__device__ int   g_pack[T_STEPS * E_EDGES];       // src | rel<<18
__device__ unsigned g_snkey[T_STEPS * SNK];       // sorted (node<<11 | entry)
__device__ int   g_snhead[T_STEPS * N_ENT];       // first index in snkey, or -1
__device__ float g_u[NROWS * DIM];
__device__ __nv_bfloat16 g_ubf[NROWS * DIM];
__device__ __nv_bfloat16 g_cbf[(size_t)C_PAD * DIM];
__device__ float g_pos[NROWS];
__device__ float g_sumexp[NROWS];

// ---------------- batched CSR build (all 16 steps at once) ----------------

__global__ void k_cnt_all(const int* __restrict__ dst) {
    long i = (long)blockIdx.x * blockDim.x + threadIdx.x;
    if (i < (long)T_STEPS * E_EDGES) {
        int t = (int)(i / E_EDGES);
        atomicAdd(&g_cnt[(size_t)t * N_ENT + dst[i]], 1);   // RED (no return)
    }
}

__global__ void k_scan1() {
    __shared__ int sh[SCAN_BS];
    int b = blockIdx.x, t = blockIdx.y, tid = threadIdx.x;
    int i = b * SCAN_BS + tid;
    int v = (i < N_ENT) ? g_cnt[(size_t)t * N_ENT + i] : 0;
    sh[tid] = v;
    __syncthreads();
    #pragma unroll
    for (int o = 1; o < SCAN_BS; o <<= 1) {
        int tv = (tid >= o) ? sh[tid - o] : 0;
        __syncthreads();
        sh[tid] += tv;
        __syncthreads();
    }
    if (i < N_ENT) g_off[(size_t)t * N_ENT + i] = sh[tid] - v;   // local exclusive
    if (tid == SCAN_BS - 1) g_bsum[t][b] = sh[tid];
}

__global__ void k_scan2() {
    __shared__ int sh[SCAN_BS];
    int t = blockIdx.x, tid = threadIdx.x;
    int v = (tid < NB) ? g_bsum[t][tid] : 0;
    sh[tid] = v;
    __syncthreads();
    #pragma unroll
    for (int o = 1; o < SCAN_BS; o <<= 1) {
        int tv = (tid >= o) ? sh[tid - o] : 0;
        __syncthreads();
        sh[tid] += tv;
        __syncthreads();
    }
    if (tid < NB) g_bsum[t][tid] = sh[tid] - v;  // exclusive block sums
}

// fill: slot = (local off advanced atomically) + block-sum
__global__ void k_fill_all(const int* __restrict__ src, const int* __restrict__ dst,
                           const int* __restrict__ rel) {
    long i = (long)blockIdx.x * blockDim.x + threadIdx.x;
    if (i >= (long)T_STEPS * E_EDGES) return;
    int t = (int)(i / E_EDGES);
    int d = dst[i];
    int slot = atomicAdd(&g_off[(size_t)t * N_ENT + d], 1) + g_bsum[t][d >> 9];
    g_pack[(size_t)t * E_EDGES + slot] = src[i] | (rel[i] << 18);
}

// ---------------- snap tables: sorted keys + per-node head index ----------

__global__ void k_snapsort(const int* __restrict__ seeds) {
    __shared__ unsigned sh[SNK];
    int t = blockIdx.x, tid = threadIdx.x;
    #pragma unroll
    for (int p = 0; p < 2; p++) {
        int e = tid + p * 1024;
        unsigned key = 0xFFFFFFFFu;
        if (e < TWIN * S_SEEDS) {
            int j = e >> 8, s = e & 255;
            int tt = t + j;
            if (tt < T_STEPS)
                key = ((unsigned)seeds[tt * S_SEEDS + s] << 11) | (unsigned)e;
        }
        sh[e] = key;
    }
    __syncthreads();
    for (int k = 2; k <= SNK; k <<= 1) {
        for (int j2 = k >> 1; j2 > 0; j2 >>= 1) {
            #pragma unroll
            for (int p = 0; p < 2; p++) {
                int i = tid + p * 1024;
                int ixj = i ^ j2;
                if (ixj > i) {
                    bool up = ((i & k) == 0);
                    unsigned a = sh[i], b = sh[ixj];
                    if ((a > b) == up) { sh[i] = b; sh[ixj] = a; }
                }
            }
            __syncthreads();
        }
    }
    #pragma unroll
    for (int p = 0; p < 2; p++) {
        int e = tid + p * 1024;
        unsigned key = sh[e];
        g_snkey[t * SNK + e] = key;
        if (key != 0xFFFFFFFFu) {
            unsigned node = key >> 11;
            if (e == 0 || (sh[e - 1] >> 11) != node)
                g_snhead[(size_t)t * N_ENT + node] = e;
        }
    }
}

// ---------------- initial fp32 -> fp16 conversion of ent_emb ----------------

__global__ void k_cvt_n(const float* __restrict__ ent, __half* __restrict__ out) {
    long i = (long)blockIdx.x * blockDim.x + threadIdx.x;   // over ND/2
    if (i >= (long)(ND / 2)) return;
    float2 v = ((const float2*)ent)[i];
    ((__half2*)out)[i] = __floats2half2_rn(v.x, v.y);
}

// ---- fused update: copy-or-(gather+mean+residual) + direct-lookup snapshot ----
// Cache policy: own-row prev reads and pack reads are read-once -> __ldcs
// (evict-first), so L2 stays biased toward the freshly written cur buffer
// (next step's prev) and the random gather targets.

__global__ void __launch_bounds__(256) k_update(const __half* __restrict__ prev,
                                                __half* __restrict__ cur,
                                                const float* __restrict__ rel_emb,
                                                const int* __restrict__ cnt,
                                                const int* __restrict__ off,
                                                const int* __restrict__ bsum,
                                                const int* __restrict__ pack,
                                                const unsigned* __restrict__ snkeys,
                                                const int* __restrict__ snhead,
                                                int t) {
    int node = (int)((blockIdx.x * blockDim.x + threadIdx.x) >> 5);
    if (node >= N_ENT) return;
    int lane = threadIdx.x & 31;
    int deg = cnt[node];
    int head = snhead[node];                 // coalesced, warp-uniform
    uint2 praw = __ldcs(((const uint2*)(prev + (size_t)node * DIM)) + lane);
    uint2 o = praw;
    if (deg > 0) {
        float2 p0 = __half22float2(*(const __half2*)&praw.x);
        float2 p1 = __half22float2(*(const __half2*)&praw.y);
        int beg = off[node] - deg + bsum[node >> 9];
        float4 sum = make_float4(0.f, 0.f, 0.f, 0.f);
        for (int i = 0; i < deg; i++) {
            int pk = __ldcs(pack + beg + i);    // warp-uniform -> broadcast
            int s = pk & 0x3FFFF;
            int r = pk >> 18;
            uint2 araw = ((const uint2*)(prev + (size_t)s * DIM))[lane];
            float2 a0 = __half22float2(*(const __half2*)&araw.x);
            float2 a1 = __half22float2(*(const __half2*)&araw.y);
            float4 b = ((const float4*)(rel_emb + (size_t)r * DIM))[lane];
            sum.x = fmaf(a0.x, b.x, sum.x);
            sum.y = fmaf(a0.y, b.y, sum.y);
            sum.z = fmaf(a1.x, b.z, sum.z);
            sum.w = fmaf(a1.y, b.w, sum.w);
        }
        float inv = 1.0f / (float)deg;
        p0.x = fmaf(sum.x, inv, p0.x);
        p0.y = fmaf(sum.y, inv, p0.y);
        p1.x = fmaf(sum.z, inv, p1.x);
        p1.y = fmaf(sum.w, inv, p1.y);
        *(__half2*)&o.x = __floats2half2_rn(p0.x, p0.y);
        *(__half2*)&o.y = __floats2half2_rn(p1.x, p1.y);
    }
    ((uint2*)(cur + (size_t)node * DIM))[lane] = o;

    // inline snapshot: direct head lookup (rare path)
    if (head >= 0) {
        float2 v0 = __half22float2(*(const __half2*)&o.x);
        float2 v1 = __half22float2(*(const __half2*)&o.y);
        float4 v = make_float4(v0.x, v0.y, v1.x, v1.y);
        int lo = head;
        do {
            unsigned kk = snkeys[lo];
            int e = (int)(kk & 0x7FFu);
            int j = e >> 8, s = e & 255;
            int tt = t + j, w = (TWIN - 1) - j;
            ((float4*)(g_snap + (((size_t)tt * TWIN + w) * S_SEEDS + s) * DIM))[lane] = v;
            lo++;
        } while (lo < SNK && (snkeys[lo] >> 11) == (unsigned)node);
    }
}

// ---------------- attention over 5 snapshots ----------------

__global__ void k_attn_all(const float* __restrict__ query_emb,
                           const int* __restrict__ seeds) {
    int s = blockIdx.x, tt = blockIdx.y, tid = threadIdx.x;
    int sd = seeds[tt * S_SEEDS + s];
    float q = query_emb[(size_t)sd * DIM + tid];
    float sv[TWIN], part[TWIN];
    #pragma unroll
    for (int tw = 0; tw < TWIN; tw++) {
        int ts = tt - (TWIN - 1) + tw;
        float v = 0.0f;
        if (ts >= 0)
            v = g_snap[(((size_t)tt * TWIN + tw) * S_SEEDS + s) * DIM + tid];
        sv[tw] = v;
        part[tw] = v * q;
    }
    __shared__ float red[TWIN][4];
    #pragma unroll
    for (int tw = 0; tw < TWIN; tw++) {
        float v = part[tw];
        #pragma unroll
        for (int o = 16; o > 0; o >>= 1) v += __shfl_down_sync(0xffffffffu, v, o);
        if ((tid & 31) == 0) red[tw][tid >> 5] = v;
    }
    __syncthreads();
    __shared__ float w[TWIN];
    if (tid == 0) {
        float att[TWIN], mx = -1e30f;
        #pragma unroll
        for (int tw = 0; tw < TWIN; tw++) {
            int ts = tt - (TWIN - 1) + tw;
            att[tw] = (ts >= 0) ? (red[tw][0] + red[tw][1] + red[tw][2] + red[tw][3])
                                : -1e30f;
            mx = fmaxf(mx, att[tw]);
        }
        float sum = 0.0f, ww[TWIN];
        #pragma unroll
        for (int tw = 0; tw < TWIN; tw++) {
            int ts = tt - (TWIN - 1) + tw;
            float ev = (ts >= 0) ? expf(att[tw] - mx) : 0.0f;
            ww[tw] = ev; sum += ev;
        }
        float invs = 1.0f / sum;
        #pragma unroll
        for (int tw = 0; tw < TWIN; tw++) w[tw] = ww[tw] * invs;
    }
    __syncthreads();
    float o = 0.0f;
    #pragma unroll
    for (int tw = 0; tw < TWIN; tw++) o = fmaf(w[tw], sv[tw], o);
    size_t oi = ((size_t)tt * S_SEEDS + s) * DIM + tid;
    g_u[oi] = o;
    g_ubf[oi] = __float2bfloat16(o);
}

// ---------------- loss kernels ----------------

__global__ void k_pos(const float* __restrict__ ent_emb,
                      const int* __restrict__ comp_idx) {
    int row = blockIdx.x, tid = threadIdx.x;
    int c = comp_idx[row];
    float v = g_u[(size_t)row * DIM + tid] *
              ent_emb[((size_t)(U_BASE + c)) * DIM + tid];
    #pragma unroll
    for (int o = 16; o > 0; o >>= 1) v += __shfl_down_sync(0xffffffffu, v, o);
    __shared__ float r4[4];
    if ((tid & 31) == 0) r4[tid >> 5] = v;
    __syncthreads();
    if (tid == 0) {
        g_pos[row] = r4[0] + r4[1] + r4[2] + r4[3];
        g_sumexp[row] = 0.0f;
    }
}

__global__ void k_cvt_c(const float* __restrict__ ent_emb) {
    long i = (long)blockIdx.x * blockDim.x + threadIdx.x;
    if (i >= (long)C_PAD * 32) return;
    long row = i >> 5; int q = (int)(i & 31);
    float4 v = (row < C_NUM)
        ? ((const float4*)(ent_emb + ((size_t)(U_BASE) + row) * DIM))[q]
        : make_float4(0.f, 0.f, 0.f, 0.f);
    __nv_bfloat162* o = (__nv_bfloat162*)(g_cbf + (size_t)row * DIM + q * 4);
    o[0] = __floats2bfloat162_rn(v.x, v.y);
    o[1] = __floats2bfloat162_rn(v.z, v.w);
}

// ---- tensor-core fused GEMM + poly-exp + row-sum (R10 BM=128 version) ----

#define SM_STRIDE 72

__global__ void __launch_bounds__(256) k_scores_mma() {
    __shared__ __nv_bfloat16 As[128][SM_STRIDE];
    __shared__ __nv_bfloat16 Bs[128][SM_STRIDE];
    __shared__ float srow[128];
    int tid = threadIdx.x;
    int lane = tid & 31, wid = tid >> 5;
    int wm = (wid & 1) * 64;
    int wn = (wid >> 1) * 32;
    int m0 = blockIdx.y * 128, c0 = blockIdx.x * 128;
    if (tid < 128) srow[tid] = 0.0f;

    float acc[4][4][4] = {};
    const __nv_bfloat16* Ag = g_ubf + (size_t)m0 * DIM;
    const __nv_bfloat16* Bg = g_cbf + (size_t)c0 * DIM;

    for (int kc = 0; kc < DIM; kc += 64) {
        #pragma unroll
        for (int i = 0; i < 4; i++) {
            int idx = tid + i * 256;
            int r = idx >> 3, q = idx & 7;
            *(uint4*)&As[r][q * 8] = *(const uint4*)(Ag + (size_t)r * DIM + kc + q * 8);
            *(uint4*)&Bs[r][q * 8] = *(const uint4*)(Bg + (size_t)r * DIM + kc + q * 8);
        }
        __syncthreads();
        #pragma unroll
        for (int kf = 0; kf < 4; kf++) {
            uint32_t a[4][4], b[2][4];
            #pragma unroll
            for (int mf = 0; mf < 4; mf++) {
                uint32_t addr = (uint32_t)__cvta_generic_to_shared(
                    &As[wm + mf * 16 + (lane & 15)][kf * 16 + (lane >> 4) * 8]);
                asm volatile("ldmatrix.sync.aligned.m8n8.x4.shared.b16 {%0,%1,%2,%3}, [%4];"
                    : "=r"(a[mf][0]), "=r"(a[mf][1]), "=r"(a[mf][2]), "=r"(a[mf][3])
                    : "r"(addr));
            }
            #pragma unroll
            for (int np = 0; np < 2; np++) {
                uint32_t addr = (uint32_t)__cvta_generic_to_shared(
                    &Bs[wn + np * 16 + ((lane >> 4) << 3) + (lane & 7)]
                       [kf * 16 + ((lane >> 3) & 1) * 8]);
                asm volatile("ldmatrix.sync.aligned.m8n8.x4.shared.b16 {%0,%1,%2,%3}, [%4];"
                    : "=r"(b[np][0]), "=r"(b[np][1]), "=r"(b[np][2]), "=r"(b[np][3])
                    : "r"(addr));
            }
            #pragma unroll
            for (int mf = 0; mf < 4; mf++)
                #pragma unroll
                for (int nf = 0; nf < 4; nf++) {
                    uint32_t b0 = b[nf >> 1][(nf & 1) * 2];
                    uint32_t b1 = b[nf >> 1][(nf & 1) * 2 + 1];
                    asm volatile(
                        "mma.sync.aligned.m16n8k16.row.col.f32.bf16.bf16.f32 "
                        "{%0,%1,%2,%3}, {%4,%5,%6,%7}, {%8,%9}, {%0,%1,%2,%3};"
                        : "+f"(acc[mf][nf][0]), "+f"(acc[mf][nf][1]),
                          "+f"(acc[mf][nf][2]), "+f"(acc[mf][nf][3])
                        : "r"(a[mf][0]), "r"(a[mf][1]), "r"(a[mf][2]), "r"(a[mf][3]),
                          "r"(b0), "r"(b1));
                }
        }
        __syncthreads();
    }

    int g = lane >> 2, t = lane & 3;
    #pragma unroll
    for (int mf = 0; mf < 4; mf++) {
        float rs0 = 0.0f, rs1 = 0.0f;
        #pragma unroll
        for (int nf = 0; nf < 4; nf++) {
            int colb = c0 + wn + nf * 8 + 2 * t;
            #pragma unroll
            for (int j = 0; j < 4; j++) {
                int col = colb + (j & 1);
                if (col < C_NUM) {
                    float x = acc[mf][nf][j];
                    float p = 1.3888889e-3f;
                    p = fmaf(p, x, 8.3333333e-3f);
                    p = fmaf(p, x, 4.1666667e-2f);
                    p = fmaf(p, x, 1.6666667e-1f);
                    p = fmaf(p, x, 0.5f);
                    p = fmaf(p, x, 1.0f);
                    p = fmaf(p, x, 1.0f);
                    if (j < 2) rs0 += p; else rs1 += p;
                }
            }
        }
        rs0 += __shfl_xor_sync(0xffffffffu, rs0, 1);
        rs0 += __shfl_xor_sync(0xffffffffu, rs0, 2);
        rs1 += __shfl_xor_sync(0xffffffffu, rs1, 1);
        rs1 += __shfl_xor_sync(0xffffffffu, rs1, 2);
        if (t == 0) {
            atomicAdd(&srow[wm + mf * 16 + g], rs0);
            atomicAdd(&srow[wm + mf * 16 + g + 8], rs1);
        }
    }
    __syncthreads();
    if (tid < 128) atomicAdd(&g_sumexp[m0 + tid], srow[tid]);
}

__global__ void k_loss(float* __restrict__ out) {
    int tid = threadIdx.x;
    double sum = 0.0;
    for (int r = tid; r < NROWS; r += 256)
        sum += (double)logf(g_sumexp[r]) - (double)g_pos[r];
    __shared__ double sh[256];
    sh[tid] = sum;
    __syncthreads();
    for (int o = 128; o > 0; o >>= 1) {
        if (tid < o) sh[tid] += sh[tid + o];
        __syncthreads();
    }
    if (tid == 0) out[0] = (float)sh[0];
}

// ---------------- launch ----------------

extern "C" void kernel_launch(void* const* d_in, const int* in_sizes, int n_in,
                              void* d_out, int out_size) {
    const float* ent   = (const float*)d_in[0];
    const float* query = (const float*)d_in[1];
    const float* rel   = (const float*)d_in[2];
    const int* esrc  = (const int*)d_in[3];
    const int* edst  = (const int*)d_in[4];
    const int* erel  = (const int*)d_in[5];
    const int* seeds = (const int*)d_in[6];
    const int* cidx  = (const int*)d_in[7];

    __half* nodes = nullptr;
    cudaGetSymbolAddress((void**)&nodes, g_nodes);
    void* cntp = nullptr;
    cudaGetSymbolAddress(&cntp, g_cnt);
    unsigned* snk = nullptr;
    cudaGetSymbolAddress((void**)&snk, g_snkey);
    void* snhp = nullptr;
    cudaGetSymbolAddress(&snhp, g_snhead);
    int* snh = (int*)snhp;

    // ---- batched CSR build for all 16 steps ----
    cudaMemsetAsync(cntp, 0, (size_t)T_STEPS * N_ENT * sizeof(int));
    cudaMemsetAsync(snhp, 0xFF, (size_t)T_STEPS * N_ENT * sizeof(int));  // -1
    long TE = (long)T_STEPS * E_EDGES;
    k_cnt_all<<<(unsigned)((TE + 255) / 256), 256>>>(edst);
    k_scan1<<<dim3(NB, T_STEPS), SCAN_BS>>>();
    k_scan2<<<T_STEPS, SCAN_BS>>>();
    k_fill_all<<<(unsigned)((TE + 255) / 256), 256>>>(esrc, edst, erel);

    // independent prep
    k_snapsort<<<T_STEPS, 1024>>>(seeds);
    k_cvt_c<<<((long)C_PAD * 32 + 255) / 256, 256>>>(ent);
    k_cvt_n<<<(unsigned)((ND / 2 + 255) / 256), 256>>>(ent, nodes);  // buf0 = half(ent)

    // ---- serial GCRNN loop: fused update+snapshot only ----
    const __half* prev = nodes;                            // buf0
    for (int t = 0; t < T_STEPS; t++) {
        __half* cur = nodes + (size_t)((t & 1) ^ 1) * ND;  // step0 -> buf1
        k_update<<<((size_t)N_ENT * 32 + 255) / 256, 256>>>(
            prev, cur, rel,
            g_cnt + (size_t)t * N_ENT,
            g_off + (size_t)t * N_ENT,
            &g_bsum[t][0],
            g_pack + (size_t)t * E_EDGES,
            snk + (size_t)t * SNK,
            snh + (size_t)t * N_ENT, t);
        prev = cur;
    }
    k_attn_all<<<dim3(S_SEEDS, T_STEPS), DIM>>>(query, seeds);
    k_pos<<<NROWS, DIM>>>(ent, cidx);
    dim3 gg(C_PAD / 128, NROWS / 128);
    k_scores_mma<<<gg, 256>>>();
    k_loss<<<1, 256>>>((float*)d_out);
}

// round 16
// speedup vs baseline: 1.1390x; 1.1390x over previous
#include <cuda_runtime.h>
#include <cuda_bf16.h>
#include <cuda_fp16.h>
#include <cstddef>
#include <cstdint>

#define N_ENT   250002
#define DIM     128
#define T_STEPS 16
#define E_EDGES 300000
#define S_SEEDS 256
#define TWIN    5
#define C_NUM   50000
#define C_PAD   50048           /* 391 * 128 */
#define U_BASE  200000
#define NROWS   (T_STEPS * S_SEEDS)

#define ND ((size_t)N_ENT * DIM)
#define SCAN_BS 512
#define NB ((N_ENT + SCAN_BS - 1) / SCAN_BS)   /* 489 */
#define SNK 2048                               /* padded snap-key table per step */

// ---- scratch (device globals) ----
__device__ __half g_nodes[2 * N_ENT * DIM];       // ping-pong node embeddings (fp16)
__device__ float g_snap[T_STEPS * TWIN * S_SEEDS * DIM]; // seed-row snapshots (fp32)
__device__ int   g_cnt[T_STEPS * N_ENT];
__device__ int   g_off[T_STEPS * N_ENT];          // local-exclusive, advanced by fill
__device__ int   g_bsum[T_STEPS][SCAN_BS];
__device__ int   g_pack[T_STEPS * E_EDGES];       // src | rel<<18
__device__ unsigned g_snkey[T_STEPS * SNK];       // sorted (node<<11 | entry)
__device__ int   g_snhead[T_STEPS * N_ENT];       // first index in snkey, or -1
__device__ float g_u[NROWS * DIM];
__device__ __nv_bfloat16 g_ubf[NROWS * DIM];
__device__ __nv_bfloat16 g_cbf[(size_t)C_PAD * DIM];
__device__ float g_pos[NROWS];
__device__ float g_sumexp[NROWS];

// ---------------- batched CSR build (all 16 steps at once) ----------------

__global__ void k_cnt_all(const int* __restrict__ dst) {
    long i = (long)blockIdx.x * blockDim.x + threadIdx.x;
    if (i < (long)T_STEPS * E_EDGES) {
        int t = (int)(i / E_EDGES);
        atomicAdd(&g_cnt[(size_t)t * N_ENT + dst[i]], 1);   // RED (no return)
    }
}

__global__ void k_scan1() {
    __shared__ int sh[SCAN_BS];
    int b = blockIdx.x, t = blockIdx.y, tid = threadIdx.x;
    int i = b * SCAN_BS + tid;
    int v = (i < N_ENT) ? g_cnt[(size_t)t * N_ENT + i] : 0;
    sh[tid] = v;
    __syncthreads();
    #pragma unroll
    for (int o = 1; o < SCAN_BS; o <<= 1) {
        int tv = (tid >= o) ? sh[tid - o] : 0;
        __syncthreads();
        sh[tid] += tv;
        __syncthreads();
    }
    if (i < N_ENT) g_off[(size_t)t * N_ENT + i] = sh[tid] - v;   // local exclusive
    if (tid == SCAN_BS - 1) g_bsum[t][b] = sh[tid];
}

__global__ void k_scan2() {
    __shared__ int sh[SCAN_BS];
    int t = blockIdx.x, tid = threadIdx.x;
    int v = (tid < NB) ? g_bsum[t][tid] : 0;
    sh[tid] = v;
    __syncthreads();
    #pragma unroll
    for (int o = 1; o < SCAN_BS; o <<= 1) {
        int tv = (tid >= o) ? sh[tid - o] : 0;
        __syncthreads();
        sh[tid] += tv;
        __syncthreads();
    }
    if (tid < NB) g_bsum[t][tid] = sh[tid] - v;  // exclusive block sums
}

// fill: slot = (local off advanced atomically) + block-sum
__global__ void k_fill_all(const int* __restrict__ src, const int* __restrict__ dst,
                           const int* __restrict__ rel) {
    long i = (long)blockIdx.x * blockDim.x + threadIdx.x;
    if (i >= (long)T_STEPS * E_EDGES) return;
    int t = (int)(i / E_EDGES);
    int d = dst[i];
    int slot = atomicAdd(&g_off[(size_t)t * N_ENT + d], 1) + g_bsum[t][d >> 9];
    g_pack[(size_t)t * E_EDGES + slot] = src[i] | (rel[i] << 18);
}

// ---------------- snap tables: sorted keys + per-node head index ----------

__global__ void k_snapsort(const int* __restrict__ seeds) {
    __shared__ unsigned sh[SNK];
    int t = blockIdx.x, tid = threadIdx.x;
    #pragma unroll
    for (int p = 0; p < 2; p++) {
        int e = tid + p * 1024;
        unsigned key = 0xFFFFFFFFu;
        if (e < TWIN * S_SEEDS) {
            int j = e >> 8, s = e & 255;
            int tt = t + j;
            if (tt < T_STEPS)
                key = ((unsigned)seeds[tt * S_SEEDS + s] << 11) | (unsigned)e;
        }
        sh[e] = key;
    }
    __syncthreads();
    for (int k = 2; k <= SNK; k <<= 1) {
        for (int j2 = k >> 1; j2 > 0; j2 >>= 1) {
            #pragma unroll
            for (int p = 0; p < 2; p++) {
                int i = tid + p * 1024;
                int ixj = i ^ j2;
                if (ixj > i) {
                    bool up = ((i & k) == 0);
                    unsigned a = sh[i], b = sh[ixj];
                    if ((a > b) == up) { sh[i] = b; sh[ixj] = a; }
                }
            }
            __syncthreads();
        }
    }
    #pragma unroll
    for (int p = 0; p < 2; p++) {
        int e = tid + p * 1024;
        unsigned key = sh[e];
        g_snkey[t * SNK + e] = key;
        if (key != 0xFFFFFFFFu) {
            unsigned node = key >> 11;
            if (e == 0 || (sh[e - 1] >> 11) != node)
                g_snhead[(size_t)t * N_ENT + node] = e;
        }
    }
}

// ---------------- initial fp32 -> fp16 conversion of ent_emb ----------------

__global__ void k_cvt_n(const float* __restrict__ ent, __half* __restrict__ out) {
    long i = (long)blockIdx.x * blockDim.x + threadIdx.x;   // over ND/2
    if (i >= (long)(ND / 2)) return;
    float2 v = ((const float2*)ent)[i];
    ((__half2*)out)[i] = __floats2half2_rn(v.x, v.y);
}

// ---- fused update: copy-or-(gather+mean+residual) + direct-lookup snapshot ----
// (exact R10 version: no cache hints — prev lines are gather targets too)

__global__ void __launch_bounds__(256) k_update(const __half* __restrict__ prev,
                                                __half* __restrict__ cur,
                                                const float* __restrict__ rel_emb,
                                                const int* __restrict__ cnt,
                                                const int* __restrict__ off,
                                                const int* __restrict__ bsum,
                                                const int* __restrict__ pack,
                                                const unsigned* __restrict__ snkeys,
                                                const int* __restrict__ snhead,
                                                int t) {
    int node = (int)((blockIdx.x * blockDim.x + threadIdx.x) >> 5);
    if (node >= N_ENT) return;
    int lane = threadIdx.x & 31;
    int deg = cnt[node];
    int head = snhead[node];                 // coalesced, warp-uniform
    uint2 praw = ((const uint2*)(prev + (size_t)node * DIM))[lane];
    uint2 o = praw;
    if (deg > 0) {
        float2 p0 = __half22float2(*(const __half2*)&praw.x);
        float2 p1 = __half22float2(*(const __half2*)&praw.y);
        int beg = off[node] - deg + bsum[node >> 9];
        float4 sum = make_float4(0.f, 0.f, 0.f, 0.f);
        for (int i = 0; i < deg; i++) {
            int pk = pack[beg + i];             // warp-uniform -> broadcast
            int s = pk & 0x3FFFF;
            int r = pk >> 18;
            uint2 araw = ((const uint2*)(prev + (size_t)s * DIM))[lane];
            float2 a0 = __half22float2(*(const __half2*)&araw.x);
            float2 a1 = __half22float2(*(const __half2*)&araw.y);
            float4 b = ((const float4*)(rel_emb + (size_t)r * DIM))[lane];
            sum.x = fmaf(a0.x, b.x, sum.x);
            sum.y = fmaf(a0.y, b.y, sum.y);
            sum.z = fmaf(a1.x, b.z, sum.z);
            sum.w = fmaf(a1.y, b.w, sum.w);
        }
        float inv = 1.0f / (float)deg;
        p0.x = fmaf(sum.x, inv, p0.x);
        p0.y = fmaf(sum.y, inv, p0.y);
        p1.x = fmaf(sum.z, inv, p1.x);
        p1.y = fmaf(sum.w, inv, p1.y);
        *(__half2*)&o.x = __floats2half2_rn(p0.x, p0.y);
        *(__half2*)&o.y = __floats2half2_rn(p1.x, p1.y);
    }
    ((uint2*)(cur + (size_t)node * DIM))[lane] = o;

    // inline snapshot: direct head lookup (rare path)
    if (head >= 0) {
        float2 v0 = __half22float2(*(const __half2*)&o.x);
        float2 v1 = __half22float2(*(const __half2*)&o.y);
        float4 v = make_float4(v0.x, v0.y, v1.x, v1.y);
        int lo = head;
        do {
            unsigned kk = snkeys[lo];
            int e = (int)(kk & 0x7FFu);
            int j = e >> 8, s = e & 255;
            int tt = t + j, w = (TWIN - 1) - j;
            ((float4*)(g_snap + (((size_t)tt * TWIN + w) * S_SEEDS + s) * DIM))[lane] = v;
            lo++;
        } while (lo < SNK && (snkeys[lo] >> 11) == (unsigned)node);
    }
}

// ---------------- attention over 5 snapshots ----------------

__global__ void k_attn_all(const float* __restrict__ query_emb,
                           const int* __restrict__ seeds) {
    int s = blockIdx.x, tt = blockIdx.y, tid = threadIdx.x;
    int sd = seeds[tt * S_SEEDS + s];
    float q = query_emb[(size_t)sd * DIM + tid];
    float sv[TWIN], part[TWIN];
    #pragma unroll
    for (int tw = 0; tw < TWIN; tw++) {
        int ts = tt - (TWIN - 1) + tw;
        float v = 0.0f;
        if (ts >= 0)
            v = g_snap[(((size_t)tt * TWIN + tw) * S_SEEDS + s) * DIM + tid];
        sv[tw] = v;
        part[tw] = v * q;
    }
    __shared__ float red[TWIN][4];
    #pragma unroll
    for (int tw = 0; tw < TWIN; tw++) {
        float v = part[tw];
        #pragma unroll
        for (int o = 16; o > 0; o >>= 1) v += __shfl_down_sync(0xffffffffu, v, o);
        if ((tid & 31) == 0) red[tw][tid >> 5] = v;
    }
    __syncthreads();
    __shared__ float w[TWIN];
    if (tid == 0) {
        float att[TWIN], mx = -1e30f;
        #pragma unroll
        for (int tw = 0; tw < TWIN; tw++) {
            int ts = tt - (TWIN - 1) + tw;
            att[tw] = (ts >= 0) ? (red[tw][0] + red[tw][1] + red[tw][2] + red[tw][3])
                                : -1e30f;
            mx = fmaxf(mx, att[tw]);
        }
        float sum = 0.0f, ww[TWIN];
        #pragma unroll
        for (int tw = 0; tw < TWIN; tw++) {
            int ts = tt - (TWIN - 1) + tw;
            float ev = (ts >= 0) ? expf(att[tw] - mx) : 0.0f;
            ww[tw] = ev; sum += ev;
        }
        float invs = 1.0f / sum;
        #pragma unroll
        for (int tw = 0; tw < TWIN; tw++) w[tw] = ww[tw] * invs;
    }
    __syncthreads();
    float o = 0.0f;
    #pragma unroll
    for (int tw = 0; tw < TWIN; tw++) o = fmaf(w[tw], sv[tw], o);
    size_t oi = ((size_t)tt * S_SEEDS + s) * DIM + tid;
    g_u[oi] = o;
    g_ubf[oi] = __float2bfloat16(o);
}

// ---------------- loss kernels ----------------

__global__ void k_pos(const float* __restrict__ ent_emb,
                      const int* __restrict__ comp_idx) {
    int row = blockIdx.x, tid = threadIdx.x;
    int c = comp_idx[row];
    float v = g_u[(size_t)row * DIM + tid] *
              ent_emb[((size_t)(U_BASE + c)) * DIM + tid];
    #pragma unroll
    for (int o = 16; o > 0; o >>= 1) v += __shfl_down_sync(0xffffffffu, v, o);
    __shared__ float r4[4];
    if ((tid & 31) == 0) r4[tid >> 5] = v;
    __syncthreads();
    if (tid == 0) {
        g_pos[row] = r4[0] + r4[1] + r4[2] + r4[3];
        g_sumexp[row] = 0.0f;
    }
}

__global__ void k_cvt_c(const float* __restrict__ ent_emb) {
    long i = (long)blockIdx.x * blockDim.x + threadIdx.x;
    if (i >= (long)C_PAD * 32) return;
    long row = i >> 5; int q = (int)(i & 31);
    float4 v = (row < C_NUM)
        ? ((const float4*)(ent_emb + ((size_t)(U_BASE) + row) * DIM))[q]
        : make_float4(0.f, 0.f, 0.f, 0.f);
    __nv_bfloat162* o = (__nv_bfloat162*)(g_cbf + (size_t)row * DIM + q * 4);
    o[0] = __floats2bfloat162_rn(v.x, v.y);
    o[1] = __floats2bfloat162_rn(v.z, v.w);
}

// ---- tensor-core fused GEMM + poly-exp + row-sum ----
// Single-phase operand load: both 64-wide k-chunks of As and Bs staged up
// front (73.7KB dynamic smem, still 2 CTAs/SM), ONE __syncthreads, then all
// 8 kf iterations uninterrupted. Tiling/grid identical to the 886us config.

#define SM_STRIDE 72
#define SMEM_SC2 (4 * 128 * SM_STRIDE * 2 + 128 * 4)   /* 74240 B */

__global__ void __launch_bounds__(256) k_scores_mma() {
    extern __shared__ char smraw[];
    __nv_bfloat16 (*As)[128][SM_STRIDE] = (__nv_bfloat16 (*)[128][SM_STRIDE])smraw;
    __nv_bfloat16 (*Bs)[128][SM_STRIDE] =
        (__nv_bfloat16 (*)[128][SM_STRIDE])(smraw + 2 * 128 * SM_STRIDE * 2);
    float* srow = (float*)(smraw + 4 * 128 * SM_STRIDE * 2);
    int tid = threadIdx.x;
    int lane = tid & 31, wid = tid >> 5;
    int wm = (wid & 1) * 64;
    int wn = (wid >> 1) * 32;
    int m0 = blockIdx.y * 128, c0 = blockIdx.x * 128;
    if (tid < 128) srow[tid] = 0.0f;

    float acc[4][4][4] = {};
    const __nv_bfloat16* Ag = g_ubf + (size_t)m0 * DIM;
    const __nv_bfloat16* Bg = g_cbf + (size_t)c0 * DIM;

    // single load phase: 2048 uint4 each for As and Bs (8 per thread each)
    #pragma unroll
    for (int i = 0; i < 8; i++) {
        int idx = tid + i * 256;           // 0..2047
        int kc2 = idx >> 10;               // which 64-col chunk
        int idx2 = idx & 1023;
        int r = idx2 >> 3, q = idx2 & 7;
        *(uint4*)&As[kc2][r][q * 8] =
            *(const uint4*)(Ag + (size_t)r * DIM + kc2 * 64 + q * 8);
        *(uint4*)&Bs[kc2][r][q * 8] =
            *(const uint4*)(Bg + (size_t)r * DIM + kc2 * 64 + q * 8);
    }
    __syncthreads();

    #pragma unroll
    for (int kc2 = 0; kc2 < 2; kc2++) {
        #pragma unroll
        for (int kf = 0; kf < 4; kf++) {
            uint32_t a[4][4], b[2][4];
            #pragma unroll
            for (int mf = 0; mf < 4; mf++) {
                uint32_t addr = (uint32_t)__cvta_generic_to_shared(
                    &As[kc2][wm + mf * 16 + (lane & 15)][kf * 16 + (lane >> 4) * 8]);
                asm volatile("ldmatrix.sync.aligned.m8n8.x4.shared.b16 {%0,%1,%2,%3}, [%4];"
                    : "=r"(a[mf][0]), "=r"(a[mf][1]), "=r"(a[mf][2]), "=r"(a[mf][3])
                    : "r"(addr));
            }
            #pragma unroll
            for (int np = 0; np < 2; np++) {
                uint32_t addr = (uint32_t)__cvta_generic_to_shared(
                    &Bs[kc2][wn + np * 16 + ((lane >> 4) << 3) + (lane & 7)]
                          [kf * 16 + ((lane >> 3) & 1) * 8]);
                asm volatile("ldmatrix.sync.aligned.m8n8.x4.shared.b16 {%0,%1,%2,%3}, [%4];"
                    : "=r"(b[np][0]), "=r"(b[np][1]), "=r"(b[np][2]), "=r"(b[np][3])
                    : "r"(addr));
            }
            #pragma unroll
            for (int mf = 0; mf < 4; mf++)
                #pragma unroll
                for (int nf = 0; nf < 4; nf++) {
                    uint32_t b0 = b[nf >> 1][(nf & 1) * 2];
                    uint32_t b1 = b[nf >> 1][(nf & 1) * 2 + 1];
                    asm volatile(
                        "mma.sync.aligned.m16n8k16.row.col.f32.bf16.bf16.f32 "
                        "{%0,%1,%2,%3}, {%4,%5,%6,%7}, {%8,%9}, {%0,%1,%2,%3};"
                        : "+f"(acc[mf][nf][0]), "+f"(acc[mf][nf][1]),
                          "+f"(acc[mf][nf][2]), "+f"(acc[mf][nf][3])
                        : "r"(a[mf][0]), "r"(a[mf][1]), "r"(a[mf][2]), "r"(a[mf][3]),
                          "r"(b0), "r"(b1));
                }
        }
    }
    __syncthreads();

    int g = lane >> 2, t = lane & 3;
    #pragma unroll
    for (int mf = 0; mf < 4; mf++) {
        float rs0 = 0.0f, rs1 = 0.0f;
        #pragma unroll
        for (int nf = 0; nf < 4; nf++) {
            int colb = c0 + wn + nf * 8 + 2 * t;
            #pragma unroll
            for (int j = 0; j < 4; j++) {
                int col = colb + (j & 1);
                if (col < C_NUM) {
                    float x = acc[mf][nf][j];
                    float p = 1.3888889e-3f;
                    p = fmaf(p, x, 8.3333333e-3f);
                    p = fmaf(p, x, 4.1666667e-2f);
                    p = fmaf(p, x, 1.6666667e-1f);
                    p = fmaf(p, x, 0.5f);
                    p = fmaf(p, x, 1.0f);
                    p = fmaf(p, x, 1.0f);
                    if (j < 2) rs0 += p; else rs1 += p;
                }
            }
        }
        rs0 += __shfl_xor_sync(0xffffffffu, rs0, 1);
        rs0 += __shfl_xor_sync(0xffffffffu, rs0, 2);
        rs1 += __shfl_xor_sync(0xffffffffu, rs1, 1);
        rs1 += __shfl_xor_sync(0xffffffffu, rs1, 2);
        if (t == 0) {
            atomicAdd(&srow[wm + mf * 16 + g], rs0);
            atomicAdd(&srow[wm + mf * 16 + g + 8], rs1);
        }
    }
    __syncthreads();
    if (tid < 128) atomicAdd(&g_sumexp[m0 + tid], srow[tid]);
}

__global__ void k_loss(float* __restrict__ out) {
    int tid = threadIdx.x;
    double sum = 0.0;
    for (int r = tid; r < NROWS; r += 256)
        sum += (double)logf(g_sumexp[r]) - (double)g_pos[r];
    __shared__ double sh[256];
    sh[tid] = sum;
    __syncthreads();
    for (int o = 128; o > 0; o >>= 1) {
        if (tid < o) sh[tid] += sh[tid + o];
        __syncthreads();
    }
    if (tid == 0) out[0] = (float)sh[0];
}

// ---------------- launch ----------------

extern "C" void kernel_launch(void* const* d_in, const int* in_sizes, int n_in,
                              void* d_out, int out_size) {
    const float* ent   = (const float*)d_in[0];
    const float* query = (const float*)d_in[1];
    const float* rel   = (const float*)d_in[2];
    const int* esrc  = (const int*)d_in[3];
    const int* edst  = (const int*)d_in[4];
    const int* erel  = (const int*)d_in[5];
    const int* seeds = (const int*)d_in[6];
    const int* cidx  = (const int*)d_in[7];

    __half* nodes = nullptr;
    cudaGetSymbolAddress((void**)&nodes, g_nodes);
    void* cntp = nullptr;
    cudaGetSymbolAddress(&cntp, g_cnt);
    unsigned* snk = nullptr;
    cudaGetSymbolAddress((void**)&snk, g_snkey);
    void* snhp = nullptr;
    cudaGetSymbolAddress(&snhp, g_snhead);
    int* snh = (int*)snhp;

    cudaFuncSetAttribute(k_scores_mma,
                         cudaFuncAttributeMaxDynamicSharedMemorySize, SMEM_SC2);

    // ---- batched CSR build for all 16 steps ----
    cudaMemsetAsync(cntp, 0, (size_t)T_STEPS * N_ENT * sizeof(int));
    cudaMemsetAsync(snhp, 0xFF, (size_t)T_STEPS * N_ENT * sizeof(int));  // -1
    long TE = (long)T_STEPS * E_EDGES;
    k_cnt_all<<<(unsigned)((TE + 255) / 256), 256>>>(edst);
    k_scan1<<<dim3(NB, T_STEPS), SCAN_BS>>>();
    k_scan2<<<T_STEPS, SCAN_BS>>>();
    k_fill_all<<<(unsigned)((TE + 255) / 256), 256>>>(esrc, edst, erel);

    // independent prep
    k_snapsort<<<T_STEPS, 1024>>>(seeds);
    k_cvt_c<<<((long)C_PAD * 32 + 255) / 256, 256>>>(ent);
    k_cvt_n<<<(unsigned)((ND / 2 + 255) / 256), 256>>>(ent, nodes);  // buf0 = half(ent)

    // ---- serial GCRNN loop: fused update+snapshot only ----
    const __half* prev = nodes;                            // buf0
    for (int t = 0; t < T_STEPS; t++) {
        __half* cur = nodes + (size_t)((t & 1) ^ 1) * ND;  // step0 -> buf1
        k_update<<<((size_t)N_ENT * 32 + 255) / 256, 256>>>(
            prev, cur, rel,
            g_cnt + (size_t)t * N_ENT,
            g_off + (size_t)t * N_ENT,
            &g_bsum[t][0],
            g_pack + (size_t)t * E_EDGES,
            snk + (size_t)t * SNK,
            snh + (size_t)t * N_ENT, t);
        prev = cur;
    }
    k_attn_all<<<dim3(S_SEEDS, T_STEPS), DIM>>>(query, seeds);
    k_pos<<<NROWS, DIM>>>(ent, cidx);
    dim3 gg(C_PAD / 128, NROWS / 128);
    k_scores_mma<<<gg, 256, SMEM_SC2>>>();
    k_loss<<<1, 256>>>((float*)d_out);
}